// round 1
// baseline (speedup 1.0000x reference)
#include <cuda_runtime.h>
#include <math.h>

// Problem constants
#define Bx 4
#define Lx 4096
#define Hx 8
#define Ex 64
#define Mx 64
#define Cx 512            // H*E
#define KP 2176           // padded folded K (>= 2049), = 17*128
#define NSPLIT 17
#define KCHUNK 128

// Static device scratch (no allocations allowed)
__device__ float g_bc[Mx * KP];                 // cos(2*pi*m*l/L), l<=2048, else 0
__device__ float g_bs[Mx * KP];                 // -sin(2*pi*m*l/L), l<=2048, else 0
__device__ float g_qs[Bx * KP * Cx];            // folded sum   q[l] + q[L-l]
__device__ float g_qd[Bx * KP * Cx];            // folded diff  q[l] - q[L-l]
__device__ float g_part[8 * NSPLIT * Mx * Cx];  // split-K partials for forward GEMM
__device__ float g_X[8 * Mx * Cx];              // X[bp][m][c], bp = b*2 + (0:Re,1:Im)
__device__ float g_res[Bx * Cx * 2 * Mx];       // res[b][c][0..63 ReS, 64..127 ImS]

// ---------------------------------------------------------------------------
// K0: build basis tables. bc[m][l] = cos(2pi m l / L); bs[m][l] = -sin(...)
// ---------------------------------------------------------------------------
__global__ void k_basis() {
    int m = blockIdx.x;
    for (int l = threadIdx.x; l < KP; l += blockDim.x) {
        float c = 0.0f, s = 0.0f;
        if (l <= 2048) {
            int r = (m * l) & (Lx - 1);
            float x = (float)r / 2048.0f;   // angle = pi * x
            sincospif(x, &s, &c);
        }
        g_bc[m * KP + l] = c;
        g_bs[m * KP + l] = -s;
    }
}

// ---------------------------------------------------------------------------
// K1: fold q along L using cos/sin symmetry.
//   qs[b][l][c] = q[l]+q[L-l] (l=1..2047), q[0] at l=0, q[2048] at l=2048
//   qd[b][l][c] = q[l]-q[L-l] (l=1..2047), 0 at l=0,2048; pads zeroed
// ---------------------------------------------------------------------------
__global__ void k_fold(const float* __restrict__ q) {
    int l = blockIdx.x;          // 0..KP-1
    int b = blockIdx.y;          // 0..3
    int c = threadIdx.x * 4;     // 128 threads * float4 = 512
    float4 vs, vd;
    if (l == 0) {
        float4 a = *(const float4*)(q + ((size_t)(b * Lx) * Cx) + c);
        vs = a; vd = make_float4(0.f, 0.f, 0.f, 0.f);
    } else if (l < 2048) {
        float4 a = *(const float4*)(q + ((size_t)(b * Lx + l) * Cx) + c);
        float4 mm = *(const float4*)(q + ((size_t)(b * Lx + (Lx - l)) * Cx) + c);
        vs = make_float4(a.x + mm.x, a.y + mm.y, a.z + mm.z, a.w + mm.w);
        vd = make_float4(a.x - mm.x, a.y - mm.y, a.z - mm.z, a.w - mm.w);
    } else if (l == 2048) {
        float4 a = *(const float4*)(q + ((size_t)(b * Lx + 2048) * Cx) + c);
        vs = a; vd = make_float4(0.f, 0.f, 0.f, 0.f);
    } else {
        vs = make_float4(0.f, 0.f, 0.f, 0.f); vd = vs;
    }
    *(float4*)(g_qs + ((size_t)b * KP + l) * Cx + c) = vs;
    *(float4*)(g_qd + ((size_t)b * KP + l) * Cx + c) = vd;
}

// ---------------------------------------------------------------------------
// K2: forward GEMM (split-K). For bp = b*2+part:
//   part 0: X_re[m][c] = sum_l bc[m][l] * qs[b][l][c]
//   part 1: X_im[m][c] = sum_l bs[m][l] * qd[b][l][c]   (bs = -sin)
// Tile: 64 m-rows x 64 c-cols per block, K chunk = 128.
// ---------------------------------------------------------------------------
__global__ void k_fwd() {
    __shared__ float As[8][68];  // [kk][j], padded to avoid conflicts
    __shared__ float Bs[8][64];  // [kk][c]
    int t = threadIdx.x;
    int tx = t & 15, ty = t >> 4;
    int ct    = blockIdx.x;      // 0..7  c-tile
    int split = blockIdx.y;      // 0..16
    int bp    = blockIdx.z;      // 0..7
    int b = bp >> 1, part = bp & 1;
    const float* A  = part ? g_bs : g_bc;
    const float* Bm = (part ? g_qd : g_qs) + (size_t)b * KP * Cx;
    int c0 = ct * 64;
    int k0 = split * KCHUNK;

    float acc[4][4];
#pragma unroll
    for (int r = 0; r < 4; r++)
#pragma unroll
        for (int cc = 0; cc < 4; cc++) acc[r][cc] = 0.f;

    for (int kc = k0; kc < k0 + KCHUNK; kc += 8) {
#pragma unroll
        for (int s = 0; s < 2; s++) {
            int i = t + 256 * s;
            int j = i >> 3, kk = i & 7;
            As[kk][j] = A[(size_t)j * KP + kc + kk];
        }
#pragma unroll
        for (int s = 0; s < 2; s++) {
            int i = t + 256 * s;
            int kk = i >> 6, c = i & 63;
            Bs[kk][c] = Bm[(size_t)(kc + kk) * Cx + c0 + c];
        }
        __syncthreads();
#pragma unroll
        for (int kk = 0; kk < 8; kk++) {
            float4 a4 = *(float4*)&As[kk][ty * 4];
            float4 b4 = *(float4*)&Bs[kk][tx * 4];
            float av[4] = {a4.x, a4.y, a4.z, a4.w};
            float bv[4] = {b4.x, b4.y, b4.z, b4.w};
#pragma unroll
            for (int r = 0; r < 4; r++)
#pragma unroll
                for (int cc = 0; cc < 4; cc++) acc[r][cc] += av[r] * bv[cc];
        }
        __syncthreads();
    }
    float* outp = g_part + ((size_t)bp * NSPLIT + split) * (Mx * Cx);
#pragma unroll
    for (int r = 0; r < 4; r++) {
        int j = ty * 4 + r;
        *(float4*)(outp + (size_t)j * Cx + c0 + tx * 4) =
            make_float4(acc[r][0], acc[r][1], acc[r][2], acc[r][3]);
    }
}

// ---------------------------------------------------------------------------
// K3: reduce split-K partials -> g_X
// ---------------------------------------------------------------------------
__global__ void k_reduce() {
    int o = blockIdx.x * blockDim.x + threadIdx.x;  // 0 .. 8*64*512-1
    int bp = o >> 15;          // 64*512 = 32768
    int jc = o & 32767;
    const float* p = g_part + (size_t)bp * NSPLIT * Mx * Cx + jc;
    float s = 0.f;
#pragma unroll
    for (int sp = 0; sp < NSPLIT; sp++) s += p[(size_t)sp * Mx * Cx];
    g_X[o] = s;
}

// ---------------------------------------------------------------------------
// K4: head mixing + irfft scaling.
//   res[b,o,e,m] = sum_i X[b,i,e,m] * (wr + i*wi)[i,o,e,m]
//   ReS = Re * (m==0 ? 1/L : 2/L); ImS = (m==0 ? 0 : Im * 2/L)
// ---------------------------------------------------------------------------
__global__ void k_mix(const float* __restrict__ wr, const float* __restrict__ wi) {
    int t = blockIdx.x * blockDim.x + threadIdx.x;  // 131072 = B*H*E*M
    int m = t & 63;
    int e = (t >> 6) & 63;
    int o = (t >> 12) & 7;
    int b = t >> 15;
    const float* Xre = g_X + ((size_t)(b * 2 + 0) * Mx + m) * Cx + e;
    const float* Xim = g_X + ((size_t)(b * 2 + 1) * Mx + m) * Cx + e;
    float re = 0.f, im = 0.f;
#pragma unroll
    for (int i = 0; i < Hx; i++) {
        float xr = Xre[i * Ex];
        float xi = Xim[i * Ex];
        size_t wIdx = (((size_t)i * Hx + o) * Ex + e) * Mx + m;
        float wre = wr[wIdx], wim = wi[wIdx];
        re += xr * wre - xi * wim;
        im += xr * wim + xi * wre;
    }
    float scR = (m == 0) ? (1.0f / Lx) : (2.0f / Lx);
    float* r = g_res + ((size_t)(b * Cx) + o * Ex + e) * 128;
    r[m] = re * scR;
    r[64 + m] = (m == 0) ? 0.f : im * (2.0f / Lx);
}

// ---------------------------------------------------------------------------
// K5: inverse synthesis with mirror writes.
//   E[l] = sum_m ReS*bc[m][l];  O[l] = sum_m ImS*bs[m][l]
//   out[l] = E+O (l=0..2047); out[L-l] = E-O (l=1..2047)
// Block: 16 rows x 128 l. 256 threads: each 2 rows x 4 l.
// ---------------------------------------------------------------------------
__global__ void k_inv(float* __restrict__ out) {
    __shared__ float a[16][128];
    int t = threadIdx.x;
    int ltile = blockIdx.x;            // 0..15
    int rowBase = blockIdx.y * 16;     // rows 0..2047 = b*512 + (o*64+e)
#pragma unroll
    for (int s = 0; s < 8; s++) {
        int i = t + 256 * s;
        a[i >> 7][i & 127] = g_res[(size_t)rowBase * 128 + i];
    }
    __syncthreads();
    int tx = t & 31, ty = t >> 5;
    int l0 = ltile * 128 + tx * 4;
    int r0 = rowBase + ty * 2;

    float4 E0 = {0,0,0,0}, O0 = {0,0,0,0}, E1 = {0,0,0,0}, O1 = {0,0,0,0};
#pragma unroll 4
    for (int m = 0; m < 64; m++) {
        float4 bc = *(const float4*)(g_bc + (size_t)m * KP + l0);
        float4 bs = *(const float4*)(g_bs + (size_t)m * KP + l0);
        float ar0 = a[ty * 2][m],     ai0 = a[ty * 2][64 + m];
        float ar1 = a[ty * 2 + 1][m], ai1 = a[ty * 2 + 1][64 + m];
        E0.x += ar0 * bc.x; E0.y += ar0 * bc.y; E0.z += ar0 * bc.z; E0.w += ar0 * bc.w;
        O0.x += ai0 * bs.x; O0.y += ai0 * bs.y; O0.z += ai0 * bs.z; O0.w += ai0 * bs.w;
        E1.x += ar1 * bc.x; E1.y += ar1 * bc.y; E1.z += ar1 * bc.z; E1.w += ar1 * bc.w;
        O1.x += ai1 * bs.x; O1.y += ai1 * bs.y; O1.z += ai1 * bs.z; O1.w += ai1 * bs.w;
    }

    {
        float4 v = make_float4(E0.x + O0.x, E0.y + O0.y, E0.z + O0.z, E0.w + O0.w);
        *(float4*)(out + (size_t)r0 * Lx + l0) = v;
        float Ev[4] = {E0.x, E0.y, E0.z, E0.w};
        float Ov[4] = {O0.x, O0.y, O0.z, O0.w};
#pragma unroll
        for (int u = 0; u < 4; u++) {
            int l = l0 + u;
            if (l > 0) out[(size_t)r0 * Lx + (Lx - l)] = Ev[u] - Ov[u];
        }
    }
    {
        int r1 = r0 + 1;
        float4 v = make_float4(E1.x + O1.x, E1.y + O1.y, E1.z + O1.z, E1.w + O1.w);
        *(float4*)(out + (size_t)r1 * Lx + l0) = v;
        float Ev[4] = {E1.x, E1.y, E1.z, E1.w};
        float Ov[4] = {O1.x, O1.y, O1.z, O1.w};
#pragma unroll
        for (int u = 0; u < 4; u++) {
            int l = l0 + u;
            if (l > 0) out[(size_t)r1 * Lx + (Lx - l)] = Ev[u] - Ov[u];
        }
    }
}

// ---------------------------------------------------------------------------
// K6: l = 2048 edge. bc[m][2048] = (-1)^m, bs = 0.
// ---------------------------------------------------------------------------
__global__ void k_edge(float* __restrict__ out) {
    int row = blockIdx.x * blockDim.x + threadIdx.x;  // 0..2047
    const float* r = g_res + (size_t)row * 128;
    float s = 0.f;
#pragma unroll
    for (int m = 0; m < 64; m += 2) { s += r[m]; s -= r[m + 1]; }
    out[(size_t)row * Lx + 2048] = s;
}

// ---------------------------------------------------------------------------
extern "C" void kernel_launch(void* const* d_in, const int* in_sizes, int n_in,
                              void* d_out, int out_size) {
    const float* q  = (const float*)d_in[0];
    // d_in[1]=k, d_in[2]=v unused by reference
    const float* wr = (const float*)d_in[3];
    const float* wi = (const float*)d_in[4];
    float* out = (float*)d_out;

    k_basis<<<64, 256>>>();
    {
        dim3 g(KP, Bx);
        k_fold<<<g, 128>>>(q);
    }
    {
        dim3 g(8, NSPLIT, 8);
        k_fwd<<<g, 256>>>();
    }
    k_reduce<<<(8 * Mx * Cx) / 256, 256>>>();
    k_mix<<<(Bx * Hx * Ex * Mx) / 256, 256>>>(wr, wi);
    {
        dim3 g(16, 128);
        k_inv<<<g, 256>>>(out);
    }
    k_edge<<<8, 256>>>(out);
}